// round 10
// baseline (speedup 1.0000x reference)
#include <cuda_runtime.h>
#include <math_constants.h>

// Problem constants (fixed by the dataset shapes)
#define B_  2
#define H_  50
#define W_  50
#define C_  256
#define R_  100
#define PH 7
#define PW 7
#define C4 (C_ / 4)   // 64 float4 lanes
#define NITEMS (B_ * R_ * PH)   // 1400 work items: (b, roi, row_bin)
#define NCTAS  (148 * 4)        // persistent workers

__device__ unsigned int g_work_counter;

__global__ void reset_counter_kernel() { g_work_counter = 0u; }

__device__ __forceinline__ float4 fmax4(float4 a, float4 b) {
    return make_float4(fmaxf(a.x, b.x), fmaxf(a.y, b.y),
                       fmaxf(a.z, b.z), fmaxf(a.w, b.w));
}

// Persistent CTAs steal (b, roi, row_bin) items from a global counter.
// Block = (64 float4-lanes, 7 column-bins): each thread computes one
// output bin of the current item. Work-stealing kills the ragged-wave
// tail that bounded the static-grid version.
__global__ void __launch_bounds__(C4 * PW, 4) roi_pool_kernel(
    const float* __restrict__ fm,     // (B, H, W, C)
    const float* __restrict__ rois,   // (B, R, 4)
    float* __restrict__ out)          // (B, R, PH, PW, C)
{
    const int c4 = threadIdx.x;              // float4 channel index
    const int j  = threadIdx.y;              // column bin
    __shared__ int s_item;

    const float4 NEG_INF4 = make_float4(-CUDART_INF_F, -CUDART_INF_F,
                                        -CUDART_INF_F, -CUDART_INF_F);

    for (;;) {
        if (threadIdx.x == 0 && threadIdx.y == 0) {
            s_item = (int)atomicAdd(&g_work_counter, 1u);
        }
        __syncthreads();
        const int item = s_item;
        __syncthreads();
        if (item >= NITEMS) return;

        const int bi = item % PH;                 // row bin
        const int r  = (item / PH) % R_;
        const int b  = item / (PH * R_);

        const float4 roi =
            *reinterpret_cast<const float4*>(rois + (size_t)(b * R_ + r) * 4);

        // Mirror reference: truncating cast of f32 products (all coords >= 0)
        const int hs = (int)(H_ * roi.x);
        const int ws = (int)(W_ * roi.y);
        const int he = (int)(H_ * roi.z);
        const int we = (int)(W_ * roi.w);

        const int sh = max((he - hs) / PH, 1);
        const int sw = max((we - ws) / PW, 1);

        // Row range for this row-bin; column range for this col-bin.
        // Last bin absorbs the remainder.
        const int y0 = hs + bi * sh;
        const int y1 = (bi == PH - 1) ? he : min(hs + (bi + 1) * sh, he);
        const int x0 = ws + j * sw;
        const int x1 = (j == PW - 1) ? we : min(ws + (j + 1) * sw, we);

        const float4* __restrict__ fmb =
            reinterpret_cast<const float4*>(fm + (size_t)b * H_ * W_ * C_) + c4;

        float4 a0 = NEG_INF4;
        float4 a1 = NEG_INF4;

        for (int y = y0; y < y1; ++y) {
            const float4* __restrict__ row = fmb + (size_t)y * (W_ * C4);
            int x = x0;
            // 2-way x-unroll: two independent accumulator chains per row
            for (; x + 1 < x1; x += 2) {
                float4 v0 = __ldg(row + (size_t)x * C4);
                float4 v1 = __ldg(row + (size_t)(x + 1) * C4);
                a0 = fmax4(a0, v0);
                a1 = fmax4(a1, v1);
            }
            if (x < x1) {
                a0 = fmax4(a0, __ldg(row + (size_t)x * C4));
            }
        }

        float4* __restrict__ o = reinterpret_cast<float4*>(
            out + ((((size_t)(b * R_ + r)) * PH + bi) * PW + j) * C_) + c4;
        *o = fmax4(a0, a1);
    }
}

extern "C" void kernel_launch(void* const* d_in, const int* in_sizes, int n_in,
                              void* d_out, int out_size)
{
    const float* fm   = (const float*)d_in[0];   // feature_map (2,50,50,256)
    const float* rois = (const float*)d_in[1];   // rois (2,100,4)
    float* out = (float*)d_out;                  // (2,100,7,7,256)

    (void)in_sizes; (void)n_in; (void)out_size;

    reset_counter_kernel<<<1, 1>>>();
    dim3 grid(NCTAS);
    dim3 block(C4, PW);
    roi_pool_kernel<<<grid, block>>>(fm, rois, out);
}

// round 11
// speedup vs baseline: 1.1194x; 1.1194x over previous
#include <cuda_runtime.h>
#include <math_constants.h>

// Problem constants (fixed by the dataset shapes)
#define B_  2
#define H_  50
#define W_  50
#define C_  256
#define R_  100
#define PH 7
#define PW 7
#define C4 (C_ / 4)   // 64 float4 lanes
#define WC4 (W_ * C4)

__device__ __forceinline__ float4 fmax4(float4 a, float4 b) {
    return make_float4(fmaxf(a.x, b.x), fmaxf(a.y, b.y),
                       fmaxf(a.z, b.z), fmaxf(a.w, b.w));
}

// One block per (b, roi, row_bin). Block = (64 float4-lanes, 7 column-bins):
// each thread computes exactly one output bin. Inner reduction issues a
// 2x4 predicated patch (8 independent LDG.128 in flight) per y-step to
// maximize MLP; predicates are warp-uniform (j constant per warp).
__global__ void __launch_bounds__(C4 * PW, 3) roi_pool_kernel(
    const float* __restrict__ fm,     // (B, H, W, C)
    const float* __restrict__ rois,   // (B, R, 4)
    float* __restrict__ out)          // (B, R, PH, PW, C)
{
    const int blk = blockIdx.x;
    const int bi = blk % PH;                 // row bin
    const int r  = (blk / PH) % R_;
    const int b  = blk / (PH * R_);
    const int c4 = threadIdx.x;              // float4 channel index
    const int j  = threadIdx.y;              // column bin

    const float4 roi = *reinterpret_cast<const float4*>(rois + (size_t)(b * R_ + r) * 4);

    // Mirror reference: truncating cast of f32 products (all coords >= 0)
    const int hs = (int)(H_ * roi.x);
    const int ws = (int)(W_ * roi.y);
    const int he = (int)(H_ * roi.z);
    const int we = (int)(W_ * roi.w);

    const int sh = max((he - hs) / PH, 1);
    const int sw = max((we - ws) / PW, 1);

    // Row range for this row-bin; column range for this col-bin.
    // Last bin absorbs the remainder.
    const int y0 = hs + bi * sh;
    const int y1 = (bi == PH - 1) ? he : min(hs + (bi + 1) * sh, he);
    const int x0 = ws + j * sw;
    const int x1 = (j == PW - 1) ? we : min(ws + (j + 1) * sw, we);

    const float4* __restrict__ fmb =
        reinterpret_cast<const float4*>(fm + (size_t)b * H_ * W_ * C_) + c4;

    const float4 NEG_INF4 = make_float4(-CUDART_INF_F, -CUDART_INF_F,
                                        -CUDART_INF_F, -CUDART_INF_F);
    float4 a0 = NEG_INF4;
    float4 a1 = NEG_INF4;

    for (int y = y0; y < y1; y += 2) {
        const float4* __restrict__ row0 = fmb + (size_t)y * WC4 + (size_t)x0 * C4;
        const float4* __restrict__ row1 = row0 + WC4;
        const bool p1 = (y + 1 < y1);
        const int w = x1 - x0;

        // 2x4 predicated patch: 8 independent loads batched before any wait.
        #pragma unroll
        for (int dx = 0; dx < 4; ++dx) {
            const bool px = dx < w;
            float4 v0 = px        ? __ldg(row0 + (size_t)dx * C4) : NEG_INF4;
            float4 v1 = (px && p1)? __ldg(row1 + (size_t)dx * C4) : NEG_INF4;
            a0 = fmax4(a0, v0);
            a1 = fmax4(a1, v1);
        }
        // x tail (only the last column bin can exceed width 4; <= 6 extra)
        for (int dx = 4; dx < w; ++dx) {
            a0 = fmax4(a0, __ldg(row0 + (size_t)dx * C4));
            if (p1) a1 = fmax4(a1, __ldg(row1 + (size_t)dx * C4));
        }
    }

    float4* __restrict__ o = reinterpret_cast<float4*>(
        out + ((((size_t)(b * R_ + r)) * PH + bi) * PW + j) * C_) + c4;
    *o = fmax4(a0, a1);
}

extern "C" void kernel_launch(void* const* d_in, const int* in_sizes, int n_in,
                              void* d_out, int out_size)
{
    const float* fm   = (const float*)d_in[0];   // feature_map (2,50,50,256)
    const float* rois = (const float*)d_in[1];   // rois (2,100,4)
    float* out = (float*)d_out;                  // (2,100,7,7,256)

    (void)in_sizes; (void)n_in; (void)out_size;

    dim3 grid(B_ * R_ * PH);
    dim3 block(C4, PW);
    roi_pool_kernel<<<grid, block>>>(fm, rois, out);
}